// round 4
// baseline (speedup 1.0000x reference)
#include <cuda_runtime.h>
#include <cmath>

// Problem constants
#define LSTEPS 47
#define RR 24
#define OO 24
#define BB 64
#define EMB 128
#define HH 256
#define M1 1536        // RR * BB
#define MALL 72192     // LSTEPS * M1

#define OUT_ALL_ELEMS 36962304   // M1 * LSTEPS * 512
#define HID_ELEMS 393216         // BB * 24 * HH

// Scratch
__device__ float d_xy[(size_t)MALL * 256];    // [x | y] packed tf32
__device__ float d_qkv[(size_t)MALL * 384];
__device__ float d_att[(size_t)MALL * 128];   // tf32-rounded
__device__ float d_pre[(size_t)MALL * 1536];  // gate-interleaved layout
__device__ float d_ht[2 * M1 * 512];          // tf32 state ping-pong [h_row|h_col]
__device__ float d_Wt[1536 * 768];            // tf32 W, rows gate-interleaved
__device__ float d_biasp[1536];               // permuted fp32 bias
__device__ float d_inwt[384 * 128];
__device__ float d_outwt[128 * 128];

__device__ __forceinline__ unsigned f2tf(float x) {
    unsigned u; asm("cvt.rna.tf32.f32 %0, %1;" : "=r"(u) : "f"(x)); return u;
}
__device__ __forceinline__ float f2tff(float x) { return __uint_as_float(f2tf(x)); }
__device__ __forceinline__ float4 tf4(float4 v) {
    return make_float4(f2tff(v.x), f2tff(v.y), f2tff(v.z), f2tff(v.w));
}

// ---------------------------------------------------------------------------
__global__ void cvt_kernel(const float* __restrict__ src, float* __restrict__ dst, int n4) {
    int i = blockIdx.x * 256 + threadIdx.x;
    if (i >= n4) return;
    ((float4*)dst)[i] = tf4(((const float4*)src)[i]);
}

// Permute W rows into gate-interleaved order + tf32 round; also permute Bias.
// new row n = ch*6 + gate ; orig row = gate*256 + ch
__global__ void permute_w_kernel(const float* __restrict__ W, float* __restrict__ Wt,
                                 const float* __restrict__ Bias, float* __restrict__ biasp) {
    int idx = blockIdx.x * 256 + threadIdx.x;   // 1536 * 192
    if (idx >= 1536 * 192) return;
    int c4 = idx % 192;
    int n  = idx / 192;
    int g6 = n % 6;
    int ch = n / 6;
    int orig = g6 * 256 + ch;
    ((float4*)(Wt + (size_t)n * 768))[c4] = tf4(((const float4*)(W + (size_t)orig * 768))[c4]);
    if (c4 == 0) biasp[n] = Bias[orig];
}

// ---------------------------------------------------------------------------
// build x (tf32): xy[m*256 + i] = input[b, l-r, r, i] (zero outside)
// ---------------------------------------------------------------------------
__global__ void build_x_kernel(const float* __restrict__ input, float* __restrict__ xy) {
    int idx = blockIdx.x * 256 + threadIdx.x;
    if (idx >= MALL * 32) return;
    int c = idx & 31;
    int m = idx >> 5;
    int b = m & 63;
    int t = m >> 6;
    int r = t % RR;
    int l = t / RR;
    int o = l - r;
    float4 v = make_float4(0.f, 0.f, 0.f, 0.f);
    if (o >= 0 && o < OO)
        v = tf4(((const float4*)(input + (size_t)((b * OO + o) * RR + r) * EMB))[c]);
    ((float4*)(xy + (size_t)m * 256))[c] = v;
}

// ---------------------------------------------------------------------------
// MMA / cp.async primitives
// ---------------------------------------------------------------------------
__device__ __forceinline__ void mma_tf32(float* d, const unsigned* a, const unsigned* b) {
    asm volatile(
        "mma.sync.aligned.m16n8k8.row.col.f32.tf32.tf32.f32 "
        "{%0,%1,%2,%3}, {%4,%5,%6,%7}, {%8,%9}, {%0,%1,%2,%3};\n"
        : "+f"(d[0]), "+f"(d[1]), "+f"(d[2]), "+f"(d[3])
        : "r"(a[0]), "r"(a[1]), "r"(a[2]), "r"(a[3]), "r"(b[0]), "r"(b[1]));
}
__device__ __forceinline__ void cpasync16(float* dst, const float* src) {
    unsigned saddr = (unsigned)__cvta_generic_to_shared(dst);
    asm volatile("cp.async.cg.shared.global [%0], [%1], 16;\n" :: "r"(saddr), "l"(src));
}
__device__ __forceinline__ float sigf(float x) { return 1.f / (1.f + __expf(-x)); }

// ===========================================================================
// Generic TF32 GEMM (128x128 tile) — used for precompute stage
// ===========================================================================
#define STAGE_F 4096

__global__ __launch_bounds__(256, 2)
void gemm_mma(const float* __restrict__ A, int lda,
              const float* __restrict__ Bw, int ldb,
              const float* __restrict__ bias,
              float* __restrict__ C, int ldc, int K, int round_out)
{
    extern __shared__ float sm[];
    int tid  = threadIdx.x;
    int lane = tid & 31;
    int warp = tid >> 5;
    int wm = (warp >> 2) * 64;
    int wn = (warp & 3) * 32;
    int g  = lane >> 2;
    int tg = lane & 3;
    int m0 = blockIdx.y * 128;
    int n0 = blockIdx.x * 128;

    int prow   = tid >> 2;
    int pchunk = (tid & 3) << 2;
    int psw    = ((prow >> 1) & 3) << 2;
    int dA = prow * 16 + (pchunk ^ psw);
    const float* Ag   = A  + (size_t)(m0 + prow) * lda + pchunk;
    const float* Ag64 = Ag + (size_t)64 * lda;
    const float* Bg   = Bw + (size_t)(n0 + prow) * ldb + pchunk;
    const float* Bg64 = Bg + (size_t)64 * ldb;

    auto prefetch = [&](int st, int k0) {
        float* sA = sm + st * STAGE_F;
        float* sB = sA + 2048;
        cpasync16(sA + dA,        Ag   + k0);
        cpasync16(sA + dA + 1024, Ag64 + k0);
        cpasync16(sB + dA,        Bg   + k0);
        cpasync16(sB + dA + 1024, Bg64 + k0);
        asm volatile("cp.async.commit_group;\n" ::);
    };

    float acc[4][4][4];
#pragma unroll
    for (int i = 0; i < 4; ++i)
#pragma unroll
        for (int j = 0; j < 4; ++j)
#pragma unroll
            for (int q = 0; q < 4; ++q) acc[i][j][q] = 0.f;

    int ktiles = K >> 4;
    prefetch(0, 0); prefetch(1, 16); prefetch(2, 32);
    int swz = ((g >> 1) & 3) << 2;

    for (int kt = 0; kt < ktiles; ++kt) {
        asm volatile("cp.async.wait_group 2;\n" ::);
        __syncthreads();
        if (kt + 3 < ktiles) prefetch((kt + 3) & 3, (kt + 3) << 4);
        else asm volatile("cp.async.commit_group;\n" ::);

        const unsigned* sA = (const unsigned*)(sm + (kt & 3) * STAGE_F);
        const unsigned* sB = sA + 2048;
        const unsigned* pA = sA + (wm + g) * 16;
        const unsigned* pB = sB + (wn + g) * 16;

#pragma unroll
        for (int ks = 0; ks < 2; ++ks) {
            int c0 = (ks * 8 + tg) ^ swz;
            int c4 = (ks * 8 + tg + 4) ^ swz;
            unsigned af[4][4], bf[4][2];
#pragma unroll
            for (int i = 0; i < 4; ++i) {
                af[i][0] = pA[i * 256 + c0];
                af[i][1] = pA[i * 256 + 128 + c0];
                af[i][2] = pA[i * 256 + c4];
                af[i][3] = pA[i * 256 + 128 + c4];
            }
#pragma unroll
            for (int j = 0; j < 4; ++j) {
                bf[j][0] = pB[j * 128 + c0];
                bf[j][1] = pB[j * 128 + c4];
            }
#pragma unroll
            for (int i = 0; i < 4; ++i)
#pragma unroll
                for (int j = 0; j < 4; ++j)
                    mma_tf32(acc[i][j], af[i], bf[j]);
        }
    }

#pragma unroll
    for (int i = 0; i < 4; ++i) {
        int r0 = m0 + wm + i * 16 + g;
#pragma unroll
        for (int j = 0; j < 4; ++j) {
            int c = n0 + wn + j * 8 + 2 * tg;
            float v0 = acc[i][j][0], v1 = acc[i][j][1];
            float v2 = acc[i][j][2], v3 = acc[i][j][3];
            if (bias) {
                float2 bb = *(const float2*)&bias[c];
                v0 += bb.x; v1 += bb.y; v2 += bb.x; v3 += bb.y;
            }
            if (round_out) {
                v0 = f2tff(v0); v1 = f2tff(v1); v2 = f2tff(v2); v3 = f2tff(v3);
            }
            *(float2*)&C[(size_t)r0 * ldc + c]       = make_float2(v0, v1);
            *(float2*)&C[(size_t)(r0 + 8) * ldc + c] = make_float2(v2, v3);
        }
    }
}

// ===========================================================================
// Fused scan step: g = pre[s] + ht @ W[:, :512]ᵀ (interleaved), gate epilogue.
// Tile 96(M) x 192(N); grid (8, 16) = 128 blocks. K = 512.
// ===========================================================================
#define SC_STAGE 4608              // floats per stage: A 96*16 + B 192*16
#define SC_SMEMF 18816             // bounce: 96 * 196

__global__ __launch_bounds__(256, 1)
void gemm_scan(const float* __restrict__ hin,      // tf32 state [M1][512]
               const float* __restrict__ Wt,       // interleaved tf32 [1536][768]
               const float* __restrict__ biasp,    // permuted fp32 [1536]
               const float* __restrict__ preS,     // pre + s*M1*1536 (interleaved)
               float* __restrict__ hout,           // next tf32 state
               float* __restrict__ out_all,
               float* __restrict__ out_col,
               float* __restrict__ out_row,
               int s)
{
    extern __shared__ float sm[];
    int tid  = threadIdx.x;
    int lane = tid & 31;
    int warp = tid >> 5;
    int wm = (warp >> 2) * 48;          // 2 warps along m (0,48)
    int wn = (warp & 3) * 48;           // 4 warps along n (0,48,96,144)
    int g  = lane >> 2;
    int tg = lane & 3;
    int m0 = blockIdx.y * 96;
    int n0 = blockIdx.x * 192;

    int prow   = tid >> 2;              // 0..63
    int pchunk = (tid & 3) << 2;
    int psw    = ((prow >> 1) & 3) << 2;
    int dA = prow * 16 + (pchunk ^ psw);     // +64 rows -> +1024, +128 rows -> +2048
    const float* Ag    = hin + (size_t)(m0 + prow) * 512 + pchunk;
    const float* Ag64  = Ag + (size_t)64 * 512;
    const float* Bg    = Wt  + (size_t)(n0 + prow) * 768 + pchunk;
    const float* Bg64  = Bg + (size_t)64 * 768;
    const float* Bg128 = Bg + (size_t)128 * 768;
    bool pA2 = (tid < 128);             // rows 64..95 of A

    auto prefetch = [&](int st, int k0) {
        float* sA = sm + st * SC_STAGE;
        float* sB = sA + 1536;
        cpasync16(sA + dA, Ag + k0);
        if (pA2) cpasync16(sA + dA + 1024, Ag64 + k0);
        cpasync16(sB + dA,        Bg    + k0);
        cpasync16(sB + dA + 1024, Bg64  + k0);
        cpasync16(sB + dA + 2048, Bg128 + k0);
        asm volatile("cp.async.commit_group;\n" ::);
    };

    float acc[3][6][4];
#pragma unroll
    for (int i = 0; i < 3; ++i)
#pragma unroll
        for (int j = 0; j < 6; ++j)
#pragma unroll
            for (int q = 0; q < 4; ++q) acc[i][j][q] = 0.f;

    prefetch(0, 0); prefetch(1, 16); prefetch(2, 32);
    int swz = ((g >> 1) & 3) << 2;

    for (int kt = 0; kt < 32; ++kt) {
        asm volatile("cp.async.wait_group 2;\n" ::);
        __syncthreads();
        if (kt + 3 < 32) prefetch((kt + 3) & 3, (kt + 3) << 4);
        else asm volatile("cp.async.commit_group;\n" ::);

        const unsigned* sA = (const unsigned*)(sm + (kt & 3) * SC_STAGE);
        const unsigned* sB = sA + 1536;
        const unsigned* pA = sA + (wm + g) * 16;
        const unsigned* pB = sB + (wn + g) * 16;

#pragma unroll
        for (int ks = 0; ks < 2; ++ks) {
            int c0 = (ks * 8 + tg) ^ swz;
            int c4 = (ks * 8 + tg + 4) ^ swz;
            unsigned af[3][4], bf[6][2];
#pragma unroll
            for (int i = 0; i < 3; ++i) {
                af[i][0] = pA[i * 256 + c0];
                af[i][1] = pA[i * 256 + 128 + c0];
                af[i][2] = pA[i * 256 + c4];
                af[i][3] = pA[i * 256 + 128 + c4];
            }
#pragma unroll
            for (int j = 0; j < 6; ++j) {
                bf[j][0] = pB[j * 128 + c0];
                bf[j][1] = pB[j * 128 + c4];
            }
#pragma unroll
            for (int i = 0; i < 3; ++i)
#pragma unroll
                for (int j = 0; j < 6; ++j)
                    mma_tf32(acc[i][j], af[i], bf[j]);
        }
    }

    asm volatile("cp.async.wait_group 0;\n" ::);
    __syncthreads();    // all mainloop smem reads done before bounce overwrite

    // Epilogue phase 1: acc + pre + masked bias -> smem bounce [96][196]
#pragma unroll
    for (int i = 0; i < 3; ++i) {
        int row = wm + 16 * i + g;
        int rG  = m0 + row;
        bool b0 = (((rG) >> 6) <= s) && (s < RR);
        bool b1 = (((rG + 8) >> 6) <= s) && (s < RR);
#pragma unroll
        for (int j = 0; j < 6; ++j) {
            int col = wn + 8 * j + 2 * tg;
            float2 p0 = *(const float2*)&preS[(size_t)rG * 1536 + n0 + col];
            float2 p1 = *(const float2*)&preS[(size_t)(rG + 8) * 1536 + n0 + col];
            float2 bb = *(const float2*)&biasp[n0 + col];
            float v0 = acc[i][j][0] + p0.x + (b0 ? bb.x : 0.f);
            float v1 = acc[i][j][1] + p0.y + (b0 ? bb.y : 0.f);
            float v2 = acc[i][j][2] + p1.x + (b1 ? bb.x : 0.f);
            float v3 = acc[i][j][3] + p1.y + (b1 ? bb.y : 0.f);
            *(float2*)&sm[row * 196 + col]       = make_float2(v0, v1);
            *(float2*)&sm[(row + 8) * 196 + col] = make_float2(v2, v3);
        }
    }
    __syncthreads();

    // Epilogue phase 2: gates. 192 threads: one (row, 16-channel half) each.
    if (tid < 192) {
        int row = tid >> 1;
        int chh = (tid & 1) * 16;
        int m = m0 + row;
        int r = m >> 6;
        int b = m & 63;
        int chg = blockIdx.x * 32 + chh;   // global channel base (16 channels)

        float q[96];
        const float4* gq = (const float4*)&sm[row * 196 + chh * 6];
#pragma unroll
        for (int v = 0; v < 24; ++v) ((float4*)q)[v] = gq[v];

        float hrold[16], hcold[16];
#pragma unroll
        for (int v = 0; v < 4; ++v) {
            ((float4*)hrold)[v] = *(const float4*)&hin[(size_t)m * 512 + chg + 4 * v];
            ((float4*)hcold)[v] = *(const float4*)&hin[(size_t)m * 512 + 256 + chg + 4 * v];
        }

        float hr[16], hc[16];
#pragma unroll
        for (int c = 0; c < 16; ++c) {
            float ug_r = sigf(q[6 * c + 0]);
            float og_r = sigf(q[6 * c + 1]);
            float ug_c = sigf(q[6 * c + 2]);
            float og_c = sigf(q[6 * c + 3]);
            float ig_r = tanhf(q[6 * c + 4]);
            float ig_c = tanhf(q[6 * c + 5]);
            hr[c] = tanhf((1.f - ug_r) * hrold[c] + ug_r * ig_r) * og_r;
            hc[c] = tanhf((1.f - ug_c) * hcold[c] + ug_c * ig_c) * og_c;
        }

        int r2 = (r + 1) % RR;
        int mc = r2 * BB + b;
        float* ob = out_all + ((size_t)m * LSTEPS + s) * 512;
#pragma unroll
        for (int v = 0; v < 4; ++v) {
            float4 h4 = ((float4*)hr)[v];
            float4 c4 = ((float4*)hc)[v];
            *(float4*)&hout[(size_t)m * 512 + chg + 4 * v]        = tf4(h4);
            *(float4*)&hout[(size_t)mc * 512 + 256 + chg + 4 * v] = tf4(c4);
            *(float4*)&ob[chg + 4 * v]       = h4;
            *(float4*)&ob[256 + chg + 4 * v] = c4;
        }
        if (s >= OO - 1) {
            int t2 = s - (OO - 1);
            if (r == t2) {
#pragma unroll
                for (int v = 0; v < 4; ++v)
                    *(float4*)&out_row[(size_t)(b * RR + t2) * HH + chg + 4 * v] = ((float4*)hr)[v];
            }
            if (r == RR - 1) {
#pragma unroll
                for (int v = 0; v < 4; ++v)
                    *(float4*)&out_col[(size_t)(b * OO + t2) * HH + chg + 4 * v] = ((float4*)hc)[v];
            }
        }
    }
}

// ---------------------------------------------------------------------------
// MHA core per (l, b, h)
// ---------------------------------------------------------------------------
__global__ __launch_bounds__(768)
void attn_kernel(const float* __restrict__ qkv, const float* __restrict__ mask,
                 float* __restrict__ att) {
    int bid = blockIdx.x;
    int h = bid & 1;
    int b = (bid >> 1) & 63;
    int l = bid >> 7;

    __shared__ float ks[RR][64];
    __shared__ float vs[RR][64];
    int tid = threadIdx.x;
    for (int idx = tid; idx < RR * 64; idx += 768) {
        int s = idx >> 6, d = idx & 63;
        int base = ((l * RR + s) * BB + b) * 384 + h * 64 + d;
        ks[s][d] = qkv[base + 128];
        vs[s][d] = qkv[base + 256];
    }
    __syncthreads();

    int w = tid >> 5, lane = tid & 31;
    if (w >= RR) return;
    int r = w;
    int mq = ((l * RR + r) * BB + b) * 384 + h * 64;
    float q0 = qkv[mq + lane];
    float q1 = qkv[mq + 32 + lane];

    float sc = 0.f;
#pragma unroll
    for (int s = 0; s < RR; ++s) {
        float part = q0 * ks[s][lane] + q1 * ks[s][lane + 32];
#pragma unroll
        for (int off = 16; off; off >>= 1)
            part += __shfl_xor_sync(0xffffffffu, part, off);
        if (lane == s) sc = part;
    }
    float sco = (lane < RR) ? sc * 0.125f + mask[r * RR + lane] : -INFINITY;
    float mx = sco;
#pragma unroll
    for (int off = 16; off; off >>= 1)
        mx = fmaxf(mx, __shfl_xor_sync(0xffffffffu, mx, off));
    float e = expf(sco - mx);
    float sum = e;
#pragma unroll
    for (int off = 16; off; off >>= 1)
        sum += __shfl_xor_sync(0xffffffffu, sum, off);
    float p = e / sum;

    float acc0 = 0.f, acc1 = 0.f;
#pragma unroll
    for (int s = 0; s < RR; ++s) {
        float ps = __shfl_sync(0xffffffffu, p, s);
        acc0 = fmaf(ps, vs[s][lane], acc0);
        acc1 = fmaf(ps, vs[s][lane + 32], acc1);
    }
    int mo = ((l * RR + r) * BB + b) * EMB + h * 64;
    att[mo + lane]      = f2tff(acc0);
    att[mo + 32 + lane] = f2tff(acc1);
}

// ---------------------------------------------------------------------------
// Launch
// ---------------------------------------------------------------------------
extern "C" void kernel_launch(void* const* d_in, const int* in_sizes, int n_in,
                              void* d_out, int out_size) {
    const float* input = (const float*)d_in[0];
    const float* mask  = (const float*)d_in[1];
    const float* W     = (const float*)d_in[2];
    const float* Bias  = (const float*)d_in[3];
    const float* inw   = (const float*)d_in[4];
    const float* inb   = (const float*)d_in[5];
    const float* outw  = (const float*)d_in[6];
    const float* outb  = (const float*)d_in[7];
    float* out = (float*)d_out;

    float *xy, *qkv, *att, *pre, *ht, *Wt, *biasp, *inwt, *outwt;
    cudaGetSymbolAddress((void**)&xy,    d_xy);
    cudaGetSymbolAddress((void**)&qkv,   d_qkv);
    cudaGetSymbolAddress((void**)&att,   d_att);
    cudaGetSymbolAddress((void**)&pre,   d_pre);
    cudaGetSymbolAddress((void**)&ht,    d_ht);
    cudaGetSymbolAddress((void**)&Wt,    d_Wt);
    cudaGetSymbolAddress((void**)&biasp, d_biasp);
    cudaGetSymbolAddress((void**)&inwt,  d_inwt);
    cudaGetSymbolAddress((void**)&outwt, d_outwt);

    cudaFuncSetAttribute(gemm_mma, cudaFuncAttributeMaxDynamicSharedMemorySize, 65536);
    cudaFuncSetAttribute(gemm_scan, cudaFuncAttributeMaxDynamicSharedMemorySize, SC_SMEMF * 4);
    const int SMEMB = 65536;

    // 0) one-time weight prep
    permute_w_kernel<<<(1536 * 192 + 255) / 256, 256>>>(W, Wt, Bias, biasp);
    cvt_kernel<<<(384 * 128 / 4 + 255) / 256, 256>>>(inw, inwt, 384 * 128 / 4);
    cvt_kernel<<<(128 * 128 / 4 + 255) / 256, 256>>>(outw, outwt, 128 * 128 / 4);

    // 1) x (tf32)
    build_x_kernel<<<(MALL * 32 + 255) / 256, 256>>>(input, xy);

    // 2) qkv = x @ in_proj_wᵀ + b
    gemm_mma<<<dim3(3, MALL / 128), 256, SMEMB>>>(xy, 256, inwt, EMB, inb,
                                                  qkv, 384, EMB, 0);

    // 3) attention
    attn_kernel<<<LSTEPS * BB * 2, 768>>>(qkv, mask, att);

    // 4) y = att @ out_proj_wᵀ + b -> xy[:,128:256] (tf32)
    gemm_mma<<<dim3(1, MALL / 128), 256, SMEMB>>>(att, EMB, outwt, EMB, outb,
                                                  xy + 128, 256, EMB, 1);

    // 5) pre = [x|y] @ W[:, 512:768]ᵀ (interleaved rows)
    gemm_mma<<<dim3(12, MALL / 128), 256, SMEMB>>>(xy, 256, Wt + 512, 768, nullptr,
                                                   pre, 1536, 256, 0);

    // 6) zero initial state (buffer 0)
    cudaMemsetAsync(ht, 0, (size_t)M1 * 512 * sizeof(float));

    // 7) fused sequential scan
    for (int s = 0; s < LSTEPS; ++s) {
        const float* hin = ht + (size_t)(s & 1) * M1 * 512;
        float* hout      = ht + (size_t)((s + 1) & 1) * M1 * 512;
        gemm_scan<<<dim3(8, 16), 256, SC_SMEMF * 4>>>(
            hin, Wt, biasp, pre + (size_t)s * M1 * 1536, hout,
            out, out + OUT_ALL_ELEMS, out + OUT_ALL_ELEMS + HID_ELEMS, s);
    }
}

// round 5
// speedup vs baseline: 1.0541x; 1.0541x over previous
#include <cuda_runtime.h>
#include <cmath>

// Problem constants
#define LSTEPS 47
#define RR 24
#define OO 24
#define BB 64
#define EMB 128
#define HH 256
#define M1 1536        // RR * BB
#define MALL 72192     // LSTEPS * M1

#define OUT_ALL_ELEMS 36962304   // M1 * LSTEPS * 512
#define HID_ELEMS 393216         // BB * 24 * HH

// Scratch
__device__ float d_xy[(size_t)MALL * 256];    // [x | y] packed tf32
__device__ float d_qkv[(size_t)MALL * 384];
__device__ float d_att[(size_t)MALL * 128];   // tf32-rounded
__device__ float d_pre[(size_t)MALL * 1536];
__device__ float d_ht[2 * M1 * 512];          // tf32 state ping-pong [h_row|h_col]
__device__ float d_g[M1 * 1536];
__device__ float d_Wt[1536 * 768];            // tf32-rounded W
__device__ float d_inwt[384 * 128];
__device__ float d_outwt[128 * 128];

__device__ __forceinline__ unsigned f2tf(float x) {
    unsigned u; asm("cvt.rna.tf32.f32 %0, %1;" : "=r"(u) : "f"(x)); return u;
}
__device__ __forceinline__ float f2tff(float x) { return __uint_as_float(f2tf(x)); }
__device__ __forceinline__ float4 tf4(float4 v) {
    return make_float4(f2tff(v.x), f2tff(v.y), f2tff(v.z), f2tff(v.w));
}

// ---------------------------------------------------------------------------
__global__ void cvt_kernel(const float* __restrict__ src, float* __restrict__ dst, int n4) {
    int i = blockIdx.x * 256 + threadIdx.x;
    if (i >= n4) return;
    ((float4*)dst)[i] = tf4(((const float4*)src)[i]);
}

// ---------------------------------------------------------------------------
// build x (tf32): xy[m*256 + i] = input[b, l-r, r, i] (zero outside)
// ---------------------------------------------------------------------------
__global__ void build_x_kernel(const float* __restrict__ input, float* __restrict__ xy) {
    int idx = blockIdx.x * 256 + threadIdx.x;
    if (idx >= MALL * 32) return;
    int c = idx & 31;
    int m = idx >> 5;
    int b = m & 63;
    int t = m >> 6;
    int r = t % RR;
    int l = t / RR;
    int o = l - r;
    float4 v = make_float4(0.f, 0.f, 0.f, 0.f);
    if (o >= 0 && o < OO)
        v = tf4(((const float4*)(input + (size_t)((b * OO + o) * RR + r) * EMB))[c]);
    ((float4*)(xy + (size_t)m * 256))[c] = v;
}

// ---------------------------------------------------------------------------
// MMA / cp.async primitives
// ---------------------------------------------------------------------------
__device__ __forceinline__ void mma_tf32(float* d, const unsigned* a, const unsigned* b) {
    asm volatile(
        "mma.sync.aligned.m16n8k8.row.col.f32.tf32.tf32.f32 "
        "{%0,%1,%2,%3}, {%4,%5,%6,%7}, {%8,%9}, {%0,%1,%2,%3};\n"
        : "+f"(d[0]), "+f"(d[1]), "+f"(d[2]), "+f"(d[3])
        : "r"(a[0]), "r"(a[1]), "r"(a[2]), "r"(a[3]), "r"(b[0]), "r"(b[1]));
}
__device__ __forceinline__ void cpasync16(float* dst, const float* src) {
    unsigned saddr = (unsigned)__cvta_generic_to_shared(dst);
    asm volatile("cp.async.cg.shared.global [%0], [%1], 16;\n" :: "r"(saddr), "l"(src));
}

// ===========================================================================
// Generic TF32 GEMM (128x128 tile, 4-stage cp.async) — precompute stage
// ===========================================================================
#define STAGE_F 4096

__global__ __launch_bounds__(256, 2)
void gemm_mma(const float* __restrict__ A, int lda,
              const float* __restrict__ Bw, int ldb,
              const float* __restrict__ bias,
              float* __restrict__ C, int ldc, int K, int round_out)
{
    extern __shared__ float sm[];
    int tid  = threadIdx.x;
    int lane = tid & 31;
    int warp = tid >> 5;
    int wm = (warp >> 2) * 64;
    int wn = (warp & 3) * 32;
    int g  = lane >> 2;
    int tg = lane & 3;
    int m0 = blockIdx.y * 128;
    int n0 = blockIdx.x * 128;

    int prow   = tid >> 2;
    int pchunk = (tid & 3) << 2;
    int psw    = ((prow >> 1) & 3) << 2;
    int dA = prow * 16 + (pchunk ^ psw);
    const float* Ag   = A  + (size_t)(m0 + prow) * lda + pchunk;
    const float* Ag64 = Ag + (size_t)64 * lda;
    const float* Bg   = Bw + (size_t)(n0 + prow) * ldb + pchunk;
    const float* Bg64 = Bg + (size_t)64 * ldb;

    auto prefetch = [&](int st, int k0) {
        float* sA = sm + st * STAGE_F;
        float* sB = sA + 2048;
        cpasync16(sA + dA,        Ag   + k0);
        cpasync16(sA + dA + 1024, Ag64 + k0);
        cpasync16(sB + dA,        Bg   + k0);
        cpasync16(sB + dA + 1024, Bg64 + k0);
        asm volatile("cp.async.commit_group;\n" ::);
    };

    float acc[4][4][4];
#pragma unroll
    for (int i = 0; i < 4; ++i)
#pragma unroll
        for (int j = 0; j < 4; ++j)
#pragma unroll
            for (int q = 0; q < 4; ++q) acc[i][j][q] = 0.f;

    int ktiles = K >> 4;
    prefetch(0, 0); prefetch(1, 16); prefetch(2, 32);
    int swz = ((g >> 1) & 3) << 2;

    for (int kt = 0; kt < ktiles; ++kt) {
        asm volatile("cp.async.wait_group 2;\n" ::);
        __syncthreads();
        if (kt + 3 < ktiles) prefetch((kt + 3) & 3, (kt + 3) << 4);
        else asm volatile("cp.async.commit_group;\n" ::);

        const unsigned* sA = (const unsigned*)(sm + (kt & 3) * STAGE_F);
        const unsigned* sB = sA + 2048;
        const unsigned* pA = sA + (wm + g) * 16;
        const unsigned* pB = sB + (wn + g) * 16;

#pragma unroll
        for (int ks = 0; ks < 2; ++ks) {
            int c0 = (ks * 8 + tg) ^ swz;
            int c4 = (ks * 8 + tg + 4) ^ swz;
            unsigned af[4][4], bf[4][2];
#pragma unroll
            for (int i = 0; i < 4; ++i) {
                af[i][0] = pA[i * 256 + c0];
                af[i][1] = pA[i * 256 + 128 + c0];
                af[i][2] = pA[i * 256 + c4];
                af[i][3] = pA[i * 256 + 128 + c4];
            }
#pragma unroll
            for (int j = 0; j < 4; ++j) {
                bf[j][0] = pB[j * 128 + c0];
                bf[j][1] = pB[j * 128 + c4];
            }
#pragma unroll
            for (int i = 0; i < 4; ++i)
#pragma unroll
                for (int j = 0; j < 4; ++j)
                    mma_tf32(acc[i][j], af[i], bf[j]);
        }
    }

#pragma unroll
    for (int i = 0; i < 4; ++i) {
        int r0 = m0 + wm + i * 16 + g;
#pragma unroll
        for (int j = 0; j < 4; ++j) {
            int c = n0 + wn + j * 8 + 2 * tg;
            float v0 = acc[i][j][0], v1 = acc[i][j][1];
            float v2 = acc[i][j][2], v3 = acc[i][j][3];
            if (bias) {
                float2 bb = *(const float2*)&bias[c];
                v0 += bb.x; v1 += bb.y; v2 += bb.x; v3 += bb.y;
            }
            if (round_out) {
                v0 = f2tff(v0); v1 = f2tff(v1); v2 = f2tff(v2); v3 = f2tff(v3);
            }
            *(float2*)&C[(size_t)r0 * ldc + c]       = make_float2(v0, v1);
            *(float2*)&C[(size_t)(r0 + 8) * ldc + c] = make_float2(v2, v3);
        }
    }
}

// ===========================================================================
// Scan GEMM, 128x64 tile (grid 24x12 = 288 blocks -> 2 CTAs/SM).
// g = ht @ W[:, :512]ᵀ + pre[s]. K = 512.
// ===========================================================================
#define SC2_STAGE 3072   // A 2048 + B 1024 floats per stage; 4 stages = 48KB

__global__ __launch_bounds__(256, 2)
void gemm_scan64(const float* __restrict__ A,      // ht [1536][512]
                 const float* __restrict__ Bw,     // Wt [1536][768] (cols 0..511)
                 const float* __restrict__ Cinit,  // pre + s*M1*1536
                 float* __restrict__ C)            // g [1536][1536]
{
    extern __shared__ float sm[];
    int tid  = threadIdx.x;
    int lane = tid & 31;
    int warp = tid >> 5;
    int wm = (warp >> 2) * 64;          // 0, 64
    int wn = (warp & 3) * 16;           // 0,16,32,48
    int g  = lane >> 2;
    int tg = lane & 3;
    int m0 = blockIdx.y * 128;
    int n0 = blockIdx.x * 64;

    int prow   = tid >> 2;              // 0..63
    int pchunk = (tid & 3) << 2;
    int psw    = ((prow >> 1) & 3) << 2;
    int dA = prow * 16 + (pchunk ^ psw);
    const float* Ag   = A  + (size_t)(m0 + prow) * 512 + pchunk;
    const float* Ag64 = Ag + (size_t)64 * 512;
    const float* Bg   = Bw + (size_t)(n0 + prow) * 768 + pchunk;

    auto prefetch = [&](int st, int k0) {
        float* sA = sm + st * SC2_STAGE;
        float* sB = sA + 2048;
        cpasync16(sA + dA,        Ag   + k0);
        cpasync16(sA + dA + 1024, Ag64 + k0);
        cpasync16(sB + dA,        Bg   + k0);
        asm volatile("cp.async.commit_group;\n" ::);
    };

    float acc[4][2][4];
#pragma unroll
    for (int i = 0; i < 4; ++i)
#pragma unroll
        for (int j = 0; j < 2; ++j)
#pragma unroll
            for (int q = 0; q < 4; ++q) acc[i][j][q] = 0.f;

    prefetch(0, 0); prefetch(1, 16); prefetch(2, 32);
    int swz = ((g >> 1) & 3) << 2;

    for (int kt = 0; kt < 32; ++kt) {
        asm volatile("cp.async.wait_group 2;\n" ::);
        __syncthreads();
        if (kt + 3 < 32) prefetch((kt + 3) & 3, (kt + 3) << 4);
        else asm volatile("cp.async.commit_group;\n" ::);

        const unsigned* sA = (const unsigned*)(sm + (kt & 3) * SC2_STAGE);
        const unsigned* sB = sA + 2048;
        const unsigned* pA = sA + (wm + g) * 16;
        const unsigned* pB = sB + (wn + g) * 16;

#pragma unroll
        for (int ks = 0; ks < 2; ++ks) {
            int c0 = (ks * 8 + tg) ^ swz;
            int c4 = (ks * 8 + tg + 4) ^ swz;
            unsigned af[4][4], bf[2][2];
#pragma unroll
            for (int i = 0; i < 4; ++i) {
                af[i][0] = pA[i * 256 + c0];
                af[i][1] = pA[i * 256 + 128 + c0];
                af[i][2] = pA[i * 256 + c4];
                af[i][3] = pA[i * 256 + 128 + c4];
            }
#pragma unroll
            for (int j = 0; j < 2; ++j) {
                bf[j][0] = pB[j * 128 + c0];
                bf[j][1] = pB[j * 128 + c4];
            }
#pragma unroll
            for (int i = 0; i < 4; ++i)
#pragma unroll
                for (int j = 0; j < 2; ++j)
                    mma_tf32(acc[i][j], af[i], bf[j]);
        }
    }

#pragma unroll
    for (int i = 0; i < 4; ++i) {
        int r0 = m0 + wm + i * 16 + g;
#pragma unroll
        for (int j = 0; j < 2; ++j) {
            int c = n0 + wn + j * 8 + 2 * tg;
            float2 p0 = *(const float2*)&Cinit[(size_t)r0 * 1536 + c];
            float2 p1 = *(const float2*)&Cinit[(size_t)(r0 + 8) * 1536 + c];
            *(float2*)&C[(size_t)r0 * 1536 + c] =
                make_float2(acc[i][j][0] + p0.x, acc[i][j][1] + p0.y);
            *(float2*)&C[(size_t)(r0 + 8) * 1536 + c] =
                make_float2(acc[i][j][2] + p1.x, acc[i][j][3] + p1.y);
        }
    }
}

// ---------------------------------------------------------------------------
// MHA core per (l, b, h)
// ---------------------------------------------------------------------------
__global__ __launch_bounds__(768)
void attn_kernel(const float* __restrict__ qkv, const float* __restrict__ mask,
                 float* __restrict__ att) {
    int bid = blockIdx.x;
    int h = bid & 1;
    int b = (bid >> 1) & 63;
    int l = bid >> 7;

    __shared__ float ks[RR][64];
    __shared__ float vs[RR][64];
    int tid = threadIdx.x;
    for (int idx = tid; idx < RR * 64; idx += 768) {
        int s = idx >> 6, d = idx & 63;
        int base = ((l * RR + s) * BB + b) * 384 + h * 64 + d;
        ks[s][d] = qkv[base + 128];
        vs[s][d] = qkv[base + 256];
    }
    __syncthreads();

    int w = tid >> 5, lane = tid & 31;
    if (w >= RR) return;
    int r = w;
    int mq = ((l * RR + r) * BB + b) * 384 + h * 64;
    float q0 = qkv[mq + lane];
    float q1 = qkv[mq + 32 + lane];

    float sc = 0.f;
#pragma unroll
    for (int s = 0; s < RR; ++s) {
        float part = q0 * ks[s][lane] + q1 * ks[s][lane + 32];
#pragma unroll
        for (int off = 16; off; off >>= 1)
            part += __shfl_xor_sync(0xffffffffu, part, off);
        if (lane == s) sc = part;
    }
    float sco = (lane < RR) ? sc * 0.125f + mask[r * RR + lane] : -INFINITY;
    float mx = sco;
#pragma unroll
    for (int off = 16; off; off >>= 1)
        mx = fmaxf(mx, __shfl_xor_sync(0xffffffffu, mx, off));
    float e = expf(sco - mx);
    float sum = e;
#pragma unroll
    for (int off = 16; off; off >>= 1)
        sum += __shfl_xor_sync(0xffffffffu, sum, off);
    float p = e / sum;

    float acc0 = 0.f, acc1 = 0.f;
#pragma unroll
    for (int s = 0; s < RR; ++s) {
        float ps = __shfl_sync(0xffffffffu, p, s);
        acc0 = fmaf(ps, vs[s][lane], acc0);
        acc1 = fmaf(ps, vs[s][lane + 32], acc1);
    }
    int mo = ((l * RR + r) * BB + b) * EMB + h * 64;
    att[mo + lane]      = f2tff(acc0);
    att[mo + 32 + lane] = f2tff(acc1);
}

// ---------------------------------------------------------------------------
// Gate / state update / outputs (float4-vectorized; tf32 state recurrence).
// ---------------------------------------------------------------------------
__global__ __launch_bounds__(256)
void gate_kernel(const float* __restrict__ g,
                 const float* __restrict__ hin,     // tf32 state
                 float* __restrict__ hout,          // tf32 state (next)
                 const float* __restrict__ Bias,
                 float* __restrict__ out_all,
                 float* __restrict__ out_col,
                 float* __restrict__ out_row,
                 int s) {
    int idx = blockIdx.x * 256 + threadIdx.x;   // M1*HH/4 = 98304
    int c = idx & 63;
    int m = idx >> 6;
    int b = m & 63;
    int r = m >> 6;

    const float4* G = (const float4*)(g + (size_t)m * 1536);
    float4 q[6];
#pragma unroll
    for (int t = 0; t < 6; ++t) q[t] = G[c + t * 64];
    if (r <= s && s < RR) {
        const float4* B4 = (const float4*)Bias;
#pragma unroll
        for (int t = 0; t < 6; ++t) {
            float4 bb = B4[c + t * 64];
            q[t].x += bb.x; q[t].y += bb.y; q[t].z += bb.z; q[t].w += bb.w;
        }
    }
    float* qa = (float*)q;
    float4 hro = ((const float4*)(hin + (size_t)m * 512))[c];
    float4 hco = ((const float4*)(hin + (size_t)m * 512 + 256))[c];
    float* hrp = (float*)&hro;
    float* hcp = (float*)&hco;
    float hr[4], hc[4];
#pragma unroll
    for (int t = 0; t < 4; ++t) {
        float ug_r = 1.f / (1.f + expf(-qa[t]));
        float og_r = 1.f / (1.f + expf(-qa[4 + t]));
        float ug_c = 1.f / (1.f + expf(-qa[8 + t]));
        float og_c = 1.f / (1.f + expf(-qa[12 + t]));
        float ig_r = tanhf(qa[16 + t]);
        float ig_c = tanhf(qa[20 + t]);
        hr[t] = tanhf((1.f - ug_r) * hrp[t] + ug_r * ig_r) * og_r;
        hc[t] = tanhf((1.f - ug_c) * hcp[t] + ug_c * ig_c) * og_c;
    }
    float4 hr4 = make_float4(hr[0], hr[1], hr[2], hr[3]);
    float4 hc4 = make_float4(hc[0], hc[1], hc[2], hc[3]);

    int r2 = (r + 1) % RR;
    int mc = r2 * BB + b;
    ((float4*)(hout + (size_t)m * 512))[c]        = tf4(hr4);
    ((float4*)(hout + (size_t)mc * 512 + 256))[c] = tf4(hc4);

    float* ob = out_all + ((size_t)m * LSTEPS + s) * 512;
    ((float4*)ob)[c]         = hr4;
    ((float4*)(ob + 256))[c] = hc4;

    if (s >= OO - 1) {
        int t2 = s - (OO - 1);
        if (r == t2)      ((float4*)(out_row + (size_t)(b * RR + t2) * HH))[c] = hr4;
        if (r == RR - 1)  ((float4*)(out_col + (size_t)(b * OO + t2) * HH))[c] = hc4;
    }
}

// ---------------------------------------------------------------------------
// Launch
// ---------------------------------------------------------------------------
extern "C" void kernel_launch(void* const* d_in, const int* in_sizes, int n_in,
                              void* d_out, int out_size) {
    const float* input = (const float*)d_in[0];
    const float* mask  = (const float*)d_in[1];
    const float* W     = (const float*)d_in[2];
    const float* Bias  = (const float*)d_in[3];
    const float* inw   = (const float*)d_in[4];
    const float* inb   = (const float*)d_in[5];
    const float* outw  = (const float*)d_in[6];
    const float* outb  = (const float*)d_in[7];
    float* out = (float*)d_out;

    float *xy, *qkv, *att, *pre, *ht, *g, *Wt, *inwt, *outwt;
    cudaGetSymbolAddress((void**)&xy,    d_xy);
    cudaGetSymbolAddress((void**)&qkv,   d_qkv);
    cudaGetSymbolAddress((void**)&att,   d_att);
    cudaGetSymbolAddress((void**)&pre,   d_pre);
    cudaGetSymbolAddress((void**)&ht,    d_ht);
    cudaGetSymbolAddress((void**)&g,     d_g);
    cudaGetSymbolAddress((void**)&Wt,    d_Wt);
    cudaGetSymbolAddress((void**)&inwt,  d_inwt);
    cudaGetSymbolAddress((void**)&outwt, d_outwt);

    cudaFuncSetAttribute(gemm_mma, cudaFuncAttributeMaxDynamicSharedMemorySize, 65536);
    cudaFuncSetAttribute(gemm_scan64, cudaFuncAttributeMaxDynamicSharedMemorySize, 49152);
    const int SMEMB = 65536;

    // 0) one-time tf32 rounding of weights
    cvt_kernel<<<(1536 * 768 / 4 + 255) / 256, 256>>>(W, Wt, 1536 * 768 / 4);
    cvt_kernel<<<(384 * 128 / 4 + 255) / 256, 256>>>(inw, inwt, 384 * 128 / 4);
    cvt_kernel<<<(128 * 128 / 4 + 255) / 256, 256>>>(outw, outwt, 128 * 128 / 4);

    // 1) x (tf32)
    build_x_kernel<<<(MALL * 32 + 255) / 256, 256>>>(input, xy);

    // 2) qkv = x @ in_proj_wᵀ + b
    gemm_mma<<<dim3(3, MALL / 128), 256, SMEMB>>>(xy, 256, inwt, EMB, inb,
                                                  qkv, 384, EMB, 0);

    // 3) attention
    attn_kernel<<<LSTEPS * BB * 2, 768>>>(qkv, mask, att);

    // 4) y = att @ out_proj_wᵀ + b -> xy[:,128:256] (tf32)
    gemm_mma<<<dim3(1, MALL / 128), 256, SMEMB>>>(att, EMB, outwt, EMB, outb,
                                                  xy + 128, 256, EMB, 1);

    // 5) pre = [x|y] @ W[:, 512:768]ᵀ
    gemm_mma<<<dim3(12, MALL / 128), 256, SMEMB>>>(xy, 256, Wt + 512, 768, nullptr,
                                                   pre, 1536, 256, 0);

    // 6) zero initial state (buffer 0)
    cudaMemsetAsync(ht, 0, (size_t)M1 * 512 * sizeof(float));

    // 7) sequential scan; s=0 skips the GEMM (h == 0 -> g == pre[0])
    gate_kernel<<<384, 256>>>(pre, ht, ht + (size_t)M1 * 512, Bias, out,
                              out + OUT_ALL_ELEMS,
                              out + OUT_ALL_ELEMS + HID_ELEMS, 0);
    for (int s = 1; s < LSTEPS; ++s) {
        const float* hin = ht + (size_t)(s & 1) * M1 * 512;
        float* hout      = ht + (size_t)((s + 1) & 1) * M1 * 512;
        gemm_scan64<<<dim3(24, 12), 256, SC2_STAGE * 4 * 4>>>(
            hin, Wt, pre + (size_t)s * M1 * 1536, g);
        gate_kernel<<<384, 256>>>(g, hin, hout, Bias, out,
                                  out + OUT_ALL_ELEMS,
                                  out + OUT_ALL_ELEMS + HID_ELEMS, s);
    }
}

// round 6
// speedup vs baseline: 1.1416x; 1.0830x over previous
#include <cuda_runtime.h>
#include <cmath>

// Problem constants
#define LSTEPS 47
#define RR 24
#define OO 24
#define BB 64
#define EMB 128
#define HH 256
#define M1 1536        // RR * BB
#define MALL 72192     // LSTEPS * M1

#define OUT_ALL_ELEMS 36962304   // M1 * LSTEPS * 512
#define HID_ELEMS 393216         // BB * 24 * HH

// Scratch
__device__ float d_xy[(size_t)MALL * 256];    // [x | y] packed tf32
__device__ float d_qkv[(size_t)MALL * 384];
__device__ float d_att[(size_t)MALL * 128];   // tf32-rounded
__device__ float d_pre[(size_t)MALL * 1536];
__device__ float d_ht[2 * M1 * 512];          // tf32 state ping-pong [h_row|h_col]
__device__ float d_g[M1 * 1536];
__device__ float d_Wt[1536 * 768];            // tf32-rounded W
__device__ float d_inwt[384 * 128];
__device__ float d_outwt[128 * 128];

__device__ __forceinline__ unsigned f2tf(float x) {
    unsigned u; asm("cvt.rna.tf32.f32 %0, %1;" : "=r"(u) : "f"(x)); return u;
}
__device__ __forceinline__ float f2tff(float x) { return __uint_as_float(f2tf(x)); }
__device__ __forceinline__ float4 tf4(float4 v) {
    return make_float4(f2tff(v.x), f2tff(v.y), f2tff(v.z), f2tff(v.w));
}

// ---------------------------------------------------------------------------
__global__ void cvt_kernel(const float* __restrict__ src, float* __restrict__ dst, int n4) {
    int i = blockIdx.x * 256 + threadIdx.x;
    if (i >= n4) return;
    ((float4*)dst)[i] = tf4(((const float4*)src)[i]);
}

// ---------------------------------------------------------------------------
// build x (tf32): xy[m*256 + i] = input[b, l-r, r, i] (zero outside)
// ---------------------------------------------------------------------------
__global__ void build_x_kernel(const float* __restrict__ input, float* __restrict__ xy) {
    int idx = blockIdx.x * 256 + threadIdx.x;
    if (idx >= MALL * 32) return;
    int c = idx & 31;
    int m = idx >> 5;
    int b = m & 63;
    int t = m >> 6;
    int r = t % RR;
    int l = t / RR;
    int o = l - r;
    float4 v = make_float4(0.f, 0.f, 0.f, 0.f);
    if (o >= 0 && o < OO)
        v = tf4(((const float4*)(input + (size_t)((b * OO + o) * RR + r) * EMB))[c]);
    ((float4*)(xy + (size_t)m * 256))[c] = v;
}

// ---------------------------------------------------------------------------
// MMA / cp.async primitives
// ---------------------------------------------------------------------------
__device__ __forceinline__ void mma_tf32(float* d, const unsigned* a, const unsigned* b) {
    asm volatile(
        "mma.sync.aligned.m16n8k8.row.col.f32.tf32.tf32.f32 "
        "{%0,%1,%2,%3}, {%4,%5,%6,%7}, {%8,%9}, {%0,%1,%2,%3};\n"
        : "+f"(d[0]), "+f"(d[1]), "+f"(d[2]), "+f"(d[3])
        : "r"(a[0]), "r"(a[1]), "r"(a[2]), "r"(a[3]), "r"(b[0]), "r"(b[1]));
}
__device__ __forceinline__ void cpasync16(float* dst, const float* src) {
    unsigned saddr = (unsigned)__cvta_generic_to_shared(dst);
    asm volatile("cp.async.cg.shared.global [%0], [%1], 16;\n" :: "r"(saddr), "l"(src));
}
__device__ __forceinline__ float sigf(float x) { return 1.f / (1.f + __expf(-x)); }

// ===========================================================================
// Generic TF32 GEMM (128x128 tile, 4-stage cp.async).
// C = A @ Bwᵀ (+Cinit)(+bias)(round). Used for precompute AND scan steps.
// ===========================================================================
#define STAGE_F 4096

__global__ __launch_bounds__(256, 2)
void gemm_mma(const float* __restrict__ A, int lda,
              const float* __restrict__ Bw, int ldb,
              const float* __restrict__ bias,
              const float* __restrict__ Cinit,
              float* __restrict__ C, int ldc, int K, int round_out)
{
    cudaGridDependencySynchronize();   // no-op unless launched with PDL attr
    extern __shared__ float sm[];
    int tid  = threadIdx.x;
    int lane = tid & 31;
    int warp = tid >> 5;
    int wm = (warp >> 2) * 64;
    int wn = (warp & 3) * 32;
    int g  = lane >> 2;
    int tg = lane & 3;
    int m0 = blockIdx.y * 128;
    int n0 = blockIdx.x * 128;

    int prow   = tid >> 2;
    int pchunk = (tid & 3) << 2;
    int psw    = ((prow >> 1) & 3) << 2;
    int dA = prow * 16 + (pchunk ^ psw);
    const float* Ag   = A  + (size_t)(m0 + prow) * lda + pchunk;
    const float* Ag64 = Ag + (size_t)64 * lda;
    const float* Bg   = Bw + (size_t)(n0 + prow) * ldb + pchunk;
    const float* Bg64 = Bg + (size_t)64 * ldb;

    auto prefetch = [&](int st, int k0) {
        float* sA = sm + st * STAGE_F;
        float* sB = sA + 2048;
        cpasync16(sA + dA,        Ag   + k0);
        cpasync16(sA + dA + 1024, Ag64 + k0);
        cpasync16(sB + dA,        Bg   + k0);
        cpasync16(sB + dA + 1024, Bg64 + k0);
        asm volatile("cp.async.commit_group;\n" ::);
    };

    float acc[4][4][4];
#pragma unroll
    for (int i = 0; i < 4; ++i)
#pragma unroll
        for (int j = 0; j < 4; ++j)
#pragma unroll
            for (int q = 0; q < 4; ++q) acc[i][j][q] = 0.f;

    int ktiles = K >> 4;
    prefetch(0, 0); prefetch(1, 16); prefetch(2, 32);
    int swz = ((g >> 1) & 3) << 2;

    for (int kt = 0; kt < ktiles; ++kt) {
        asm volatile("cp.async.wait_group 2;\n" ::);
        __syncthreads();
        if (kt + 3 < ktiles) prefetch((kt + 3) & 3, (kt + 3) << 4);
        else asm volatile("cp.async.commit_group;\n" ::);

        const unsigned* sA = (const unsigned*)(sm + (kt & 3) * STAGE_F);
        const unsigned* sB = sA + 2048;
        const unsigned* pA = sA + (wm + g) * 16;
        const unsigned* pB = sB + (wn + g) * 16;

#pragma unroll
        for (int ks = 0; ks < 2; ++ks) {
            int c0 = (ks * 8 + tg) ^ swz;
            int c4 = (ks * 8 + tg + 4) ^ swz;
            unsigned af[4][4], bf[4][2];
#pragma unroll
            for (int i = 0; i < 4; ++i) {
                af[i][0] = pA[i * 256 + c0];
                af[i][1] = pA[i * 256 + 128 + c0];
                af[i][2] = pA[i * 256 + c4];
                af[i][3] = pA[i * 256 + 128 + c4];
            }
#pragma unroll
            for (int j = 0; j < 4; ++j) {
                bf[j][0] = pB[j * 128 + c0];
                bf[j][1] = pB[j * 128 + c4];
            }
#pragma unroll
            for (int i = 0; i < 4; ++i)
#pragma unroll
                for (int j = 0; j < 4; ++j)
                    mma_tf32(acc[i][j], af[i], bf[j]);
        }
    }

#pragma unroll
    for (int i = 0; i < 4; ++i) {
        int r0 = m0 + wm + i * 16 + g;
#pragma unroll
        for (int j = 0; j < 4; ++j) {
            int c = n0 + wn + j * 8 + 2 * tg;
            float v0 = acc[i][j][0], v1 = acc[i][j][1];
            float v2 = acc[i][j][2], v3 = acc[i][j][3];
            if (Cinit) {
                float2 p0 = *(const float2*)&Cinit[(size_t)r0 * ldc + c];
                float2 p1 = *(const float2*)&Cinit[(size_t)(r0 + 8) * ldc + c];
                v0 += p0.x; v1 += p0.y; v2 += p1.x; v3 += p1.y;
            }
            if (bias) {
                float2 bb = *(const float2*)&bias[c];
                v0 += bb.x; v1 += bb.y; v2 += bb.x; v3 += bb.y;
            }
            if (round_out) {
                v0 = f2tff(v0); v1 = f2tff(v1); v2 = f2tff(v2); v3 = f2tff(v3);
            }
            *(float2*)&C[(size_t)r0 * ldc + c]       = make_float2(v0, v1);
            *(float2*)&C[(size_t)(r0 + 8) * ldc + c] = make_float2(v2, v3);
        }
    }
}

// ---------------------------------------------------------------------------
// MHA core per (l, b, h)
// ---------------------------------------------------------------------------
__global__ __launch_bounds__(768)
void attn_kernel(const float* __restrict__ qkv, const float* __restrict__ mask,
                 float* __restrict__ att) {
    int bid = blockIdx.x;
    int h = bid & 1;
    int b = (bid >> 1) & 63;
    int l = bid >> 7;

    __shared__ float ks[RR][64];
    __shared__ float vs[RR][64];
    int tid = threadIdx.x;
    for (int idx = tid; idx < RR * 64; idx += 768) {
        int s = idx >> 6, d = idx & 63;
        int base = ((l * RR + s) * BB + b) * 384 + h * 64 + d;
        ks[s][d] = qkv[base + 128];
        vs[s][d] = qkv[base + 256];
    }
    __syncthreads();

    int w = tid >> 5, lane = tid & 31;
    if (w >= RR) return;
    int r = w;
    int mq = ((l * RR + r) * BB + b) * 384 + h * 64;
    float q0 = qkv[mq + lane];
    float q1 = qkv[mq + 32 + lane];

    float sc = 0.f;
#pragma unroll
    for (int s = 0; s < RR; ++s) {
        float part = q0 * ks[s][lane] + q1 * ks[s][lane + 32];
#pragma unroll
        for (int off = 16; off; off >>= 1)
            part += __shfl_xor_sync(0xffffffffu, part, off);
        if (lane == s) sc = part;
    }
    float sco = (lane < RR) ? sc * 0.125f + mask[r * RR + lane] : -INFINITY;
    float mx = sco;
#pragma unroll
    for (int off = 16; off; off >>= 1)
        mx = fmaxf(mx, __shfl_xor_sync(0xffffffffu, mx, off));
    float e = expf(sco - mx);
    float sum = e;
#pragma unroll
    for (int off = 16; off; off >>= 1)
        sum += __shfl_xor_sync(0xffffffffu, sum, off);
    float p = e / sum;

    float acc0 = 0.f, acc1 = 0.f;
#pragma unroll
    for (int s = 0; s < RR; ++s) {
        float ps = __shfl_sync(0xffffffffu, p, s);
        acc0 = fmaf(ps, vs[s][lane], acc0);
        acc1 = fmaf(ps, vs[s][lane + 32], acc1);
    }
    int mo = ((l * RR + r) * BB + b) * EMB + h * 64;
    att[mo + lane]      = f2tff(acc0);
    att[mo + 32 + lane] = f2tff(acc1);
}

// ---------------------------------------------------------------------------
// Gate / state update / outputs (float4; tf32 state recurrence; fast sigmoid)
// ---------------------------------------------------------------------------
__global__ __launch_bounds__(256)
void gate_kernel(const float* __restrict__ g,
                 const float* __restrict__ hin,
                 float* __restrict__ hout,
                 const float* __restrict__ Bias,
                 float* __restrict__ out_all,
                 float* __restrict__ out_col,
                 float* __restrict__ out_row,
                 int s) {
    cudaGridDependencySynchronize();   // no-op unless launched with PDL attr
    int idx = blockIdx.x * 256 + threadIdx.x;   // M1*HH/4 = 98304
    int c = idx & 63;
    int m = idx >> 6;
    int b = m & 63;
    int r = m >> 6;

    const float4* G = (const float4*)(g + (size_t)m * 1536);
    float4 q[6];
#pragma unroll
    for (int t = 0; t < 6; ++t) q[t] = G[c + t * 64];
    if (r <= s && s < RR) {
        const float4* B4 = (const float4*)Bias;
#pragma unroll
        for (int t = 0; t < 6; ++t) {
            float4 bb = B4[c + t * 64];
            q[t].x += bb.x; q[t].y += bb.y; q[t].z += bb.z; q[t].w += bb.w;
        }
    }
    float* qa = (float*)q;
    float4 hro = ((const float4*)(hin + (size_t)m * 512))[c];
    float4 hco = ((const float4*)(hin + (size_t)m * 512 + 256))[c];
    float* hrp = (float*)&hro;
    float* hcp = (float*)&hco;
    float hr[4], hc[4];
#pragma unroll
    for (int t = 0; t < 4; ++t) {
        float ug_r = sigf(qa[t]);
        float og_r = sigf(qa[4 + t]);
        float ug_c = sigf(qa[8 + t]);
        float og_c = sigf(qa[12 + t]);
        float ig_r = tanhf(qa[16 + t]);
        float ig_c = tanhf(qa[20 + t]);
        hr[t] = tanhf((1.f - ug_r) * hrp[t] + ug_r * ig_r) * og_r;
        hc[t] = tanhf((1.f - ug_c) * hcp[t] + ug_c * ig_c) * og_c;
    }
    float4 hr4 = make_float4(hr[0], hr[1], hr[2], hr[3]);
    float4 hc4 = make_float4(hc[0], hc[1], hc[2], hc[3]);

    int r2 = (r + 1) % RR;
    int mc = r2 * BB + b;
    ((float4*)(hout + (size_t)m * 512))[c]        = tf4(hr4);
    ((float4*)(hout + (size_t)mc * 512 + 256))[c] = tf4(hc4);

    float* ob = out_all + ((size_t)m * LSTEPS + s) * 512;
    ((float4*)ob)[c]         = hr4;
    ((float4*)(ob + 256))[c] = hc4;

    if (s >= OO - 1) {
        int t2 = s - (OO - 1);
        if (r == t2)      ((float4*)(out_row + (size_t)(b * RR + t2) * HH))[c] = hr4;
        if (r == RR - 1)  ((float4*)(out_col + (size_t)(b * OO + t2) * HH))[c] = hc4;
    }
}

// ---------------------------------------------------------------------------
// Launch
// ---------------------------------------------------------------------------
extern "C" void kernel_launch(void* const* d_in, const int* in_sizes, int n_in,
                              void* d_out, int out_size) {
    const float* input = (const float*)d_in[0];
    const float* mask  = (const float*)d_in[1];
    const float* W     = (const float*)d_in[2];
    const float* Bias  = (const float*)d_in[3];
    const float* inw   = (const float*)d_in[4];
    const float* inb   = (const float*)d_in[5];
    const float* outw  = (const float*)d_in[6];
    const float* outb  = (const float*)d_in[7];
    float* out = (float*)d_out;

    float *xy, *qkv, *att, *pre, *ht, *g, *Wt, *inwt, *outwt;
    cudaGetSymbolAddress((void**)&xy,    d_xy);
    cudaGetSymbolAddress((void**)&qkv,   d_qkv);
    cudaGetSymbolAddress((void**)&att,   d_att);
    cudaGetSymbolAddress((void**)&pre,   d_pre);
    cudaGetSymbolAddress((void**)&ht,    d_ht);
    cudaGetSymbolAddress((void**)&g,     d_g);
    cudaGetSymbolAddress((void**)&Wt,    d_Wt);
    cudaGetSymbolAddress((void**)&inwt,  d_inwt);
    cudaGetSymbolAddress((void**)&outwt, d_outwt);

    cudaFuncSetAttribute(gemm_mma, cudaFuncAttributeMaxDynamicSharedMemorySize, 65536);
    const int SMEMB = 65536;

    // 0) one-time tf32 rounding of weights
    cvt_kernel<<<(1536 * 768 / 4 + 255) / 256, 256>>>(W, Wt, 1536 * 768 / 4);
    cvt_kernel<<<(384 * 128 / 4 + 255) / 256, 256>>>(inw, inwt, 384 * 128 / 4);
    cvt_kernel<<<(128 * 128 / 4 + 255) / 256, 256>>>(outw, outwt, 128 * 128 / 4);

    // 1) x (tf32)
    build_x_kernel<<<(MALL * 32 + 255) / 256, 256>>>(input, xy);

    // 2) qkv = x @ in_proj_wᵀ + b
    gemm_mma<<<dim3(3, MALL / 128), 256, SMEMB>>>(xy, 256, inwt, EMB, inb, nullptr,
                                                  qkv, 384, EMB, 0);

    // 3) attention
    attn_kernel<<<LSTEPS * BB * 2, 768>>>(qkv, mask, att);

    // 4) y = att @ out_proj_wᵀ + b -> xy[:,128:256] (tf32)
    gemm_mma<<<dim3(1, MALL / 128), 256, SMEMB>>>(att, EMB, outwt, EMB, outb, nullptr,
                                                  xy + 128, 256, EMB, 1);

    // 5) pre = [x|y] @ W[:, 512:768]ᵀ
    gemm_mma<<<dim3(12, MALL / 128), 256, SMEMB>>>(xy, 256, Wt + 512, 768, nullptr,
                                                   nullptr, pre, 1536, 256, 0);

    // 6) zero initial state (buffer 0)
    cudaMemsetAsync(ht, 0, (size_t)M1 * 512 * sizeof(float));

    // PDL launch configs for the scan loop
    cudaLaunchAttribute pdlAttr[1];
    pdlAttr[0].id = cudaLaunchAttributeProgrammaticStreamSerialization;
    pdlAttr[0].val.programmaticStreamSerializationAllowed = 1;

    cudaLaunchConfig_t cfgGemm = {};
    cfgGemm.gridDim  = dim3(12, 12);
    cfgGemm.blockDim = dim3(256);
    cfgGemm.dynamicSmemBytes = SMEMB;
    cfgGemm.stream = 0;
    cfgGemm.attrs = pdlAttr;
    cfgGemm.numAttrs = 1;

    cudaLaunchConfig_t cfgGate = {};
    cfgGate.gridDim  = dim3(384);
    cfgGate.blockDim = dim3(256);
    cfgGate.dynamicSmemBytes = 0;
    cfgGate.stream = 0;
    cfgGate.attrs = pdlAttr;
    cfgGate.numAttrs = 1;

    float* out_col = out + OUT_ALL_ELEMS;
    float* out_row = out + OUT_ALL_ELEMS + HID_ELEMS;

    // 7) sequential scan; s=0 skips the GEMM (h == 0 -> g == pre[0])
    gate_kernel<<<384, 256>>>(pre, ht, ht + (size_t)M1 * 512, Bias,
                              out, out_col, out_row, 0);
    for (int s = 1; s < LSTEPS; ++s) {
        const float* hin = ht + (size_t)(s & 1) * M1 * 512;
        float* hout      = ht + (size_t)((s + 1) & 1) * M1 * 512;
        cudaLaunchKernelEx(&cfgGemm, gemm_mma,
                           (const float*)hin, 512, (const float*)Wt, 768,
                           (const float*)nullptr,
                           (const float*)(pre + (size_t)s * M1 * 1536),
                           g, 1536, 512, 0);
        cudaLaunchKernelEx(&cfgGate, gate_kernel,
                           (const float*)g, (const float*)hin, hout,
                           Bias, out, out_col, out_row, s);
    }
}